// round 16
// baseline (speedup 1.0000x reference)
#include <cuda_runtime.h>
#include <cuda_bf16.h>
#include <cstdint>
#include <cstddef>

#define Bc 8
#define Nc 384
#define Dc 256
#define Hc 1024
#define MR (Bc*Nc)   // 3072

// ----------------------------------------------------------------- scratch
__device__ __align__(128) float g_y[(size_t)MR * Dc];
__device__ __align__(128) float g_S[MR];
__device__ __align__(128) float g_dist[(size_t)Bc * Nc * Nc];
__device__ __align__(128) float g_part[3][(size_t)MR * Dc];
__device__ float g_sumw;
__device__ __align__(128) __nv_bfloat16 g_xhi[(size_t)MR * Dc],  g_xlo[(size_t)MR * Dc];
__device__ __align__(128) __nv_bfloat16 g_w1hi[(size_t)Hc * Dc], g_w1lo[(size_t)Hc * Dc];
__device__ __align__(128) __nv_bfloat16 g_w2hi[(size_t)Dc * Hc], g_w2lo[(size_t)Dc * Hc];
__device__ __align__(128) __nv_bfloat16 g_hhi[(size_t)MR * Hc],  g_hlo[(size_t)MR * Hc];

// ----------------------------------------------------------------- helpers
__device__ __forceinline__ uint32_t smem_u32(const void* p) {
    uint32_t a;
    asm("{ .reg .u64 t; cvta.to.shared.u64 t, %1; cvt.u32.u64 %0, t; }" : "=r"(a) : "l"(p));
    return a;
}
__device__ __forceinline__ void cp_async16(uint32_t dst, const void* src) {
    asm volatile("cp.async.cg.shared.global [%0], [%1], 16;\n" :: "r"(dst), "l"(src));
}
#define CP_COMMIT()  asm volatile("cp.async.commit_group;\n" ::: "memory")
#define CP_WAIT0()   asm volatile("cp.async.wait_group 0;\n" ::: "memory")
#define CP_WAIT1()   asm volatile("cp.async.wait_group 1;\n" ::: "memory")

__device__ __forceinline__ void ldsm_x4(uint32_t* r, uint32_t addr) {
    asm volatile("ldmatrix.sync.aligned.m8n8.x4.shared.b16 {%0,%1,%2,%3}, [%4];"
        : "=r"(r[0]), "=r"(r[1]), "=r"(r[2]), "=r"(r[3]) : "r"(addr));
}
__device__ __forceinline__ void mma_bf16(float* c, const uint32_t* a, const uint32_t* b) {
    asm volatile(
        "mma.sync.aligned.m16n8k16.row.col.f32.bf16.bf16.f32 "
        "{%0,%1,%2,%3}, {%4,%5,%6,%7}, {%8,%9}, {%0,%1,%2,%3};"
        : "+f"(c[0]), "+f"(c[1]), "+f"(c[2]), "+f"(c[3])
        : "r"(a[0]), "r"(a[1]), "r"(a[2]), "r"(a[3]), "r"(b[0]), "r"(b[1]));
}
__device__ __forceinline__ uint32_t cvt_bf16x2(float hi, float lo) {
    uint32_t r; asm("cvt.rn.bf16x2.f32 %0, %1, %2;" : "=r"(r) : "f"(hi), "f"(lo)); return r;
}

// ----------------------------------------------------------------- fused prep
#define N4X ((MR * Dc) / 4)
#define N4W ((Hc * Dc) / 4)
#define N4TOT (N4X + 2 * N4W)

__global__ __launch_bounds__(512) void prep_kernel(
    const float* __restrict__ x, const float* __restrict__ w1,
    const float* __restrict__ w2, const float* __restrict__ lw)
{
    const int gid = blockIdx.x * 512 + threadIdx.x;

    const float* src;
    __nv_bfloat16 *hi, *lo;
    int idx;
    if (gid < N4X)            { src = x;  hi = g_xhi;  lo = g_xlo;  idx = gid; }
    else if (gid < N4X + N4W) { src = w1; hi = g_w1hi; lo = g_w1lo; idx = gid - N4X; }
    else                      { src = w2; hi = g_w2hi; lo = g_w2lo; idx = gid - N4X - N4W; }

    const float4 v = *(const float4*)(src + 4 * (size_t)idx);
    uint2 hw, lw4;
    hw.x = cvt_bf16x2(v.y, v.x);
    hw.y = cvt_bf16x2(v.w, v.z);
    {
        const float h0 = __uint_as_float(hw.x << 16);
        const float h1 = __uint_as_float(hw.x & 0xffff0000u);
        const float h2 = __uint_as_float(hw.y << 16);
        const float h3 = __uint_as_float(hw.y & 0xffff0000u);
        lw4.x = cvt_bf16x2(v.y - h1, v.x - h0);
        lw4.y = cvt_bf16x2(v.w - h3, v.z - h2);
    }
    *(uint2*)(hi + 4 * (size_t)idx) = hw;
    *(uint2*)(lo + 4 * (size_t)idx) = lw4;

    if (gid < MR) g_S[gid] = 0.f;

    if (blockIdx.x == 0 && threadIdx.x < 256) {
        __shared__ float sm[8];
        const int t = threadIdx.x;
        float s = lw[t];
        #pragma unroll
        for (int off = 16; off; off >>= 1) s += __shfl_xor_sync(0xffffffffu, s, off);
        if ((t & 31) == 0) sm[t >> 5] = s;
        __syncthreads();
        if (t == 0) {
            float acc = 0.f;
            #pragma unroll
            for (int k = 0; k < 8; k++) acc += sm[k];
            g_sumw = acc;
        }
    }
}

// ----------------------------------------------------------------- mma.sync GEMM
// EPI=1: full-K, relu -> hidden hi/lo bf16.
// EPI=3: split-K partial (blockIdx.z selects k-range), raw accum -> out buffer z.
template<int BM, int BN, int NW, int WMF, int K, int EPI>
__global__ void __launch_bounds__(NW * 32) mma_gemm(
    const __nv_bfloat16* __restrict__ Ahi, const __nv_bfloat16* __restrict__ Alo,
    const __nv_bfloat16* __restrict__ Bhi, const __nv_bfloat16* __restrict__ Blo,
    const float* __restrict__ bias,
    float* __restrict__ out)
{
    constexpr int NT  = NW * 32;
    constexpr int WN  = BN / (NW / WMF);
    constexpr int NN  = WN / 8;
    constexpr int TA  = BM * 80;
    constexpr int TB  = BN * 80;
    constexpr int BUF = 2 * TA + 2 * TB;
    constexpr int NCH = K / 32;
    constexpr int OUTD = (EPI == 1) ? Hc : Dc;

    extern __shared__ __align__(1024) char smem[];
    float* s_bias = (float*)smem;
    const uint32_t tiles = smem_u32(smem) + 1024;

    const int tid  = threadIdx.x;
    const int wid  = tid >> 5, lane = tid & 31;
    const int m0   = blockIdx.y * BM, n0 = blockIdx.x * BN;
    const int wm   = (wid % WMF) * 32;
    const int wn   = (wid / WMF) * WN;

    int c0 = 0, c1 = NCH;
    float* po = out;
    if (EPI == 3) {
        const int z = blockIdx.z;
        c0 = z * 11;
        c1 = (z == 2) ? NCH : c0 + 11;
        po = out + (size_t)z * ((size_t)MR * Dc);
    }

    if (EPI == 1 && tid < BN) s_bias[tid] = bias[n0 + tid];

    float cacc[2][NN][4];
    #pragma unroll
    for (int f = 0; f < 2; f++)
        #pragma unroll
        for (int g = 0; g < NN; g++)
            #pragma unroll
            for (int e = 0; e < 4; e++) cacc[f][g][e] = 0.f;

    auto issue = [&](int c) {
        const uint32_t tb = tiles + (c & 1) * BUF;
        const int kc = c * 32;
        #pragma unroll
        for (int q = 0; q < (BM * 8) / NT; ++q) {
            const int id = q * NT + tid;
            const int mat = id / (BM * 4), e = id % (BM * 4);
            const int r = e >> 2, c16 = e & 3;
            const __nv_bfloat16* src = (mat ? Alo : Ahi) + (size_t)(m0 + r) * K + kc + c16 * 8;
            cp_async16(tb + mat * TA + r * 80 + c16 * 16, src);
        }
        #pragma unroll
        for (int q = 0; q < (BN * 8) / NT; ++q) {
            const int id = q * NT + tid;
            const int mat = id / (BN * 4), e = id % (BN * 4);
            const int r = e >> 2, c16 = e & 3;
            const __nv_bfloat16* src = (mat ? Blo : Bhi) + (size_t)(n0 + r) * K + kc + c16 * 8;
            cp_async16(tb + 2 * TA + mat * TB + r * 80 + c16 * 16, src);
        }
        CP_COMMIT();
    };

    issue(c0);
    issue(c0 + 1);

    for (int c = c0; c < c1; ++c) {
        if (c + 1 < c1) { CP_WAIT1(); } else { CP_WAIT0(); }
        __syncthreads();

        const uint32_t aBase = tiles + (c & 1) * BUF;
        const uint32_t bBase = aBase + 2 * TA;

        #pragma unroll
        for (int s = 0; s < 2; ++s) {
            const int kk = s * 16;
            uint32_t aH[2][4], aL[2][4];
            #pragma unroll
            for (int f = 0; f < 2; ++f) {
                const int row = wm + f * 16 + (lane & 15);
                const int col = kk + ((lane >> 4) << 3);
                const uint32_t ad = aBase + row * 80 + col * 2;
                ldsm_x4(aH[f], ad);
                ldsm_x4(aL[f], ad + TA);
            }
            #pragma unroll
            for (int np = 0; np < NN / 2; ++np) {
                const int rowB = wn + np * 16 + (lane & 7) + ((lane & 16) >> 1);
                const int colB = kk + (lane & 8);
                const uint32_t bd = bBase + rowB * 80 + colB * 2;
                uint32_t bH[4], bL[4];
                ldsm_x4(bH, bd);
                ldsm_x4(bL, bd + TB);
                #pragma unroll
                for (int f = 0; f < 2; ++f)
                    #pragma unroll
                    for (int h = 0; h < 2; ++h)
                        mma_bf16(cacc[f][2 * np + h], aH[f], bH + 2 * h);
                #pragma unroll
                for (int f = 0; f < 2; ++f)
                    #pragma unroll
                    for (int h = 0; h < 2; ++h)
                        mma_bf16(cacc[f][2 * np + h], aH[f], bL + 2 * h);
                #pragma unroll
                for (int f = 0; f < 2; ++f)
                    #pragma unroll
                    for (int h = 0; h < 2; ++h)
                        mma_bf16(cacc[f][2 * np + h], aL[f], bH + 2 * h);
            }
        }
        __syncthreads();
        if (c + 2 < c1) issue(c + 2);
    }

    const int tq = lane >> 2, tr = lane & 3;
    #pragma unroll
    for (int f = 0; f < 2; ++f) {
        #pragma unroll
        for (int g = 0; g < NN; ++g) {
            const int col  = n0 + wn + g * 8 + tr * 2;
            const int bcol = wn + g * 8 + tr * 2;
            #pragma unroll
            for (int half = 0; half < 2; ++half) {
                const int row = m0 + wm + f * 16 + tq + half * 8;
                if (EPI == 1) {
                    float v0 = fmaxf(cacc[f][g][2 * half]     + s_bias[bcol], 0.f);
                    float v1 = fmaxf(cacc[f][g][2 * half + 1] + s_bias[bcol + 1], 0.f);
                    const uint32_t h = cvt_bf16x2(v1, v0);
                    const float h0 = __uint_as_float(h << 16);
                    const float h1 = __uint_as_float(h & 0xffff0000u);
                    const uint32_t l = cvt_bf16x2(v1 - h1, v0 - h0);
                    *(uint32_t*)&g_hhi[(size_t)row * OUTD + col] = h;
                    *(uint32_t*)&g_hlo[(size_t)row * OUTD + col] = l;
                } else {
                    *(float2*)&po[(size_t)row * OUTD + col] =
                        make_float2(cacc[f][g][2 * half], cacc[f][g][2 * half + 1]);
                }
            }
        }
    }
}

// ----------------------------------------------------------------- gemm2 epilogue
// 768 blocks x 256 thr; one float4 per thread from each of 3 partial buffers.
__global__ __launch_bounds__(256) void gemm2_epi(
    const float* __restrict__ bias, const float* __restrict__ wvec,
    float* __restrict__ xhat)
{
    const int gid = blockIdx.x * 256 + threadIdx.x;   // 0..196607
    const int row = gid >> 6, q = gid & 63;
    const int col = q * 4;

    const float4 a0 = *(const float4*)&g_part[0][4 * (size_t)gid];
    const float4 a1 = *(const float4*)&g_part[1][4 * (size_t)gid];
    const float4 a2 = *(const float4*)&g_part[2][4 * (size_t)gid];
    const float4 b4 = *(const float4*)&bias[col];
    const float4 w4 = *(const float4*)&wvec[col];

    float4 v;
    v.x = a0.x + a1.x + a2.x + b4.x;
    v.y = a0.y + a1.y + a2.y + b4.y;
    v.z = a0.z + a1.z + a2.z + b4.z;
    v.w = a0.w + a1.w + a2.w + b4.w;

    float4 yv;
    yv.x = v.x * w4.x; yv.y = v.y * w4.y; yv.z = v.z * w4.z; yv.w = v.w * w4.w;

    *(float4*)&xhat[4 * (size_t)gid] = v;
    *(float4*)&g_y [4 * (size_t)gid] = yv;

    float s = (yv.x + yv.y) + (yv.z + yv.w);
    #pragma unroll
    for (int off = 16; off; off >>= 1) s += __shfl_xor_sync(0xffffffffu, s, off);
    if ((threadIdx.x & 31) == 0) atomicAdd(&g_S[row], s);
}

// ----------------------------------------------------------------- dist1
// Symmetric tile-pair kernel, 48x48 pairs, 3x3/thread, scalar FMNMX+FADD,
// d-dimension double-buffered (2 chunks of 128 floats, pitch 132 -> conflict-free).
#define NTILE  8
#define NPAIR  36
#define TP     48
#define CHP    132
#define CHSZ   (2 * TP * CHP)

__global__ __launch_bounds__(256, 2) void dist1_kernel()
{
    extern __shared__ __align__(16) float sm[];
    float* s_tr = sm;

    const int tid = threadIdx.x;
    const int b = blockIdx.y;

    int rem = blockIdx.x, ti = 0;
    while (rem >= NTILE - ti) { rem -= NTILE - ti; ti++; }
    const int tj = ti + rem;
    const int i0 = ti * TP, j0 = tj * TP;

    const float* yb = g_y + (size_t)b * Nc * Dc;
    const uint32_t smb = smem_u32(sm);

    auto load_chunk = [&](int c) {
        const uint32_t base = smb + (uint32_t)((c & 1) * CHSZ * 4);
        const int dof = c * 128;
        #pragma unroll
        for (int q = 0; q < 6; ++q) {
            const int idx = q * 256 + tid;
            const int r = idx >> 5, u = idx & 31;
            cp_async16(base + (uint32_t)((r * 33 + u) << 4),
                       &yb[(size_t)(i0 + r) * Dc + dof + u * 4]);
        }
        #pragma unroll
        for (int q = 0; q < 6; ++q) {
            const int idx = q * 256 + tid;
            const int r = idx >> 5, u = idx & 31;
            cp_async16(base + (uint32_t)((TP * 33 + r * 33 + u) << 4),
                       &yb[(size_t)(j0 + r) * Dc + dof + u * 4]);
        }
        CP_COMMIT();
    };

    load_chunk(0);
    load_chunk(1);

    const int il = (tid >> 4) * 3;
    const int jl = (tid & 15) * 3;

    float acc[3][3];
    #pragma unroll
    for (int a = 0; a < 3; ++a)
        #pragma unroll
        for (int c = 0; c < 3; ++c) acc[a][c] = 0.f;

    #pragma unroll
    for (int ck = 0; ck < 2; ++ck) {
        if (ck == 0) { CP_WAIT1(); } else { CP_WAIT0(); }
        __syncthreads();

        const float* buf = sm + ck * CHSZ;
        const float* pi0 = buf + (il + 0) * CHP;
        const float* pi1 = buf + (il + 1) * CHP;
        const float* pi2 = buf + (il + 2) * CHP;
        const float* pj0 = buf + TP * CHP + (jl + 0) * CHP;
        const float* pj1 = buf + TP * CHP + (jl + 1) * CHP;
        const float* pj2 = buf + TP * CHP + (jl + 2) * CHP;

        #pragma unroll 8
        for (int u = 0; u < 32; ++u) {
            const int d = u << 2;
            const float4 xi0 = *(const float4*)(pi0 + d);
            const float4 xi1 = *(const float4*)(pi1 + d);
            const float4 xi2 = *(const float4*)(pi2 + d);
            const float4 xj0 = *(const float4*)(pj0 + d);
            const float4 xj1 = *(const float4*)(pj1 + d);
            const float4 xj2 = *(const float4*)(pj2 + d);
            acc[0][0] += fminf(xi0.x, xj0.x) + fminf(xi0.y, xj0.y) + fminf(xi0.z, xj0.z) + fminf(xi0.w, xj0.w);
            acc[0][1] += fminf(xi0.x, xj1.x) + fminf(xi0.y, xj1.y) + fminf(xi0.z, xj1.z) + fminf(xi0.w, xj1.w);
            acc[0][2] += fminf(xi0.x, xj2.x) + fminf(xi0.y, xj2.y) + fminf(xi0.z, xj2.z) + fminf(xi0.w, xj2.w);
            acc[1][0] += fminf(xi1.x, xj0.x) + fminf(xi1.y, xj0.y) + fminf(xi1.z, xj0.z) + fminf(xi1.w, xj0.w);
            acc[1][1] += fminf(xi1.x, xj1.x) + fminf(xi1.y, xj1.y) + fminf(xi1.z, xj1.z) + fminf(xi1.w, xj1.w);
            acc[1][2] += fminf(xi1.x, xj2.x) + fminf(xi1.y, xj2.y) + fminf(xi1.z, xj2.z) + fminf(xi1.w, xj2.w);
            acc[2][0] += fminf(xi2.x, xj0.x) + fminf(xi2.y, xj0.y) + fminf(xi2.z, xj0.z) + fminf(xi2.w, xj0.w);
            acc[2][1] += fminf(xi2.x, xj1.x) + fminf(xi2.y, xj1.y) + fminf(xi2.z, xj1.z) + fminf(xi2.w, xj1.w);
            acc[2][2] += fminf(xi2.x, xj2.x) + fminf(xi2.y, xj2.y) + fminf(xi2.z, xj2.z) + fminf(xi2.w, xj2.w);
        }
        if (ck == 0) __syncthreads();
    }

    float Si[3], Sj[3];
    #pragma unroll
    for (int a = 0; a < 3; ++a) {
        Si[a] = g_S[b * Nc + i0 + il + a];
        Sj[a] = g_S[b * Nc + j0 + jl + a];
    }
    float v[3][3];
    #pragma unroll
    for (int a = 0; a < 3; ++a)
        #pragma unroll
        for (int c = 0; c < 3; ++c)
            v[a][c] = Si[a] + Sj[c] - 2.f * acc[a][c];

    float* db = g_dist + (size_t)b * Nc * Nc;
    #pragma unroll
    for (int a = 0; a < 3; ++a)
        #pragma unroll
        for (int c = 0; c < 3; ++c)
            db[(size_t)(i0 + il + a) * Nc + j0 + jl + c] = v[a][c];

    if (ti != tj) {
        __syncthreads();
        #pragma unroll
        for (int a = 0; a < 3; ++a)
            #pragma unroll
            for (int c = 0; c < 3; ++c)
                s_tr[(jl + c) * 49 + il + a] = v[a][c];
        __syncthreads();
        #pragma unroll
        for (int a = 0; a < 3; ++a)
            #pragma unroll
            for (int c = 0; c < 3; ++c)
                db[(size_t)(j0 + il + a) * Nc + i0 + jl + c] = s_tr[(il + a) * 49 + jl + c];
    }
}

// ----------------------------------------------------------------- dist2
__global__ __launch_bounds__(256) void dist2_kernel(
    const float* __restrict__ adj,
    const int* __restrict__ box_num,
    float* __restrict__ out)
{
    const int tid = threadIdx.x;
    const int lane = tid & 31, wid = tid >> 5;
    const int b = blockIdx.y;
    const int i = blockIdx.x * 8 + wid;

    const int bn = box_num[b];
    const float sumw = g_sumw;
    const bool vi = i < bn;

    const float* drow = g_dist + ((size_t)b * Nc + i) * Nc;
    const float* arow = adj    + ((size_t)b * Nc + i) * Nc;
    float* orow       = out    + ((size_t)b * Nc + i) * Nc;

    float v[12];
    float mx = -3.4e38f;
    #pragma unroll
    for (int g = 0; g < 3; ++g) {
        const int j = g * 128 + lane * 4;
        const float4 d4 = *(const float4*)&drow[j];
        float t0 = d4.x, t1 = d4.y, t2 = d4.z, t3 = d4.w;
        if (!(vi && (j     < bn))) t0 -= sumw;
        if (!(vi && (j + 1 < bn))) t1 -= sumw;
        if (!(vi && (j + 2 < bn))) t2 -= sumw;
        if (!(vi && (j + 3 < bn))) t3 -= sumw;
        t0 = (t0 >= 0.f) ? t0 : 0.01f * t0;
        t1 = (t1 >= 0.f) ? t1 : 0.01f * t1;
        t2 = (t2 >= 0.f) ? t2 : 0.01f * t2;
        t3 = (t3 >= 0.f) ? t3 : 0.01f * t3;
        v[4 * g] = t0; v[4 * g + 1] = t1; v[4 * g + 2] = t2; v[4 * g + 3] = t3;
        mx = fmaxf(mx, fmaxf(fmaxf(t0, t1), fmaxf(t2, t3)));
    }
    #pragma unroll
    for (int off = 16; off; off >>= 1) mx = fmaxf(mx, __shfl_xor_sync(0xffffffffu, mx, off));

    float s = 0.f;
    #pragma unroll
    for (int g = 0; g < 3; ++g) {
        const int j = g * 128 + lane * 4;
        const float4 a4 = *(const float4*)&arow[j];
        const float e0 = a4.x * __expf(v[4 * g]     - mx);
        const float e1 = a4.y * __expf(v[4 * g + 1] - mx);
        const float e2 = a4.z * __expf(v[4 * g + 2] - mx);
        const float e3 = a4.w * __expf(v[4 * g + 3] - mx);
        v[4 * g] = e0; v[4 * g + 1] = e1; v[4 * g + 2] = e2; v[4 * g + 3] = e3;
        s += (e0 + e1) + (e2 + e3);
    }
    #pragma unroll
    for (int off = 16; off; off >>= 1) s += __shfl_xor_sync(0xffffffffu, s, off);
    const float inv = 1.f / s;

    #pragma unroll
    for (int g = 0; g < 3; ++g) {
        const int j = g * 128 + lane * 4;
        float4 o;
        o.x = v[4 * g]     * inv + 1e-10f;
        o.y = v[4 * g + 1] * inv + 1e-10f;
        o.z = v[4 * g + 2] * inv + 1e-10f;
        o.w = v[4 * g + 3] * inv + 1e-10f;
        *(float4*)&orow[j] = o;
    }
}

// ----------------------------------------------------------------- launch
#define SMEM1 (1024 + 2 * (2 * 64 * 80 + 2 * 128 * 80))   // 62464
#define SMEM2 (1024 + 2 * (2 * 128 * 80 + 2 * 64 * 80))   // 62464
#define SMEMD1 (2 * CHSZ * 4)                             // 101376

extern "C" void kernel_launch(void* const* d_in, const int* in_sizes, int n_in,
                              void* d_out, int out_size)
{
    const float* x       = (const float*)d_in[0];
    const float* adj     = (const float*)d_in[1];
    const int*   box_num = (const int*)d_in[2];
    const float* fc1_w   = (const float*)d_in[3];
    const float* fc1_b   = (const float*)d_in[4];
    const float* fc2_w   = (const float*)d_in[5];
    const float* fc2_b   = (const float*)d_in[6];
    const float* learn_w = (const float*)d_in[7];

    float* soft = (float*)d_out;                   // [8,384,384]
    float* xhat = soft + (size_t)Bc * Nc * Nc;     // [8,384,256]

    static __nv_bfloat16 *xhi, *xlo, *w1hi, *w1lo, *w2hi, *w2lo, *hhi, *hlo;
    static float* part;
    static bool init = false;
    if (!init) {
        cudaGetSymbolAddress((void**)&xhi,  g_xhi);
        cudaGetSymbolAddress((void**)&xlo,  g_xlo);
        cudaGetSymbolAddress((void**)&w1hi, g_w1hi);
        cudaGetSymbolAddress((void**)&w1lo, g_w1lo);
        cudaGetSymbolAddress((void**)&w2hi, g_w2hi);
        cudaGetSymbolAddress((void**)&w2lo, g_w2lo);
        cudaGetSymbolAddress((void**)&hhi,  g_hhi);
        cudaGetSymbolAddress((void**)&hlo,  g_hlo);
        cudaGetSymbolAddress((void**)&part, g_part);
        cudaFuncSetAttribute((const void*)mma_gemm<64,128,8,2,Dc,1>,
                             cudaFuncAttributeMaxDynamicSharedMemorySize, SMEM1);
        cudaFuncSetAttribute((const void*)mma_gemm<128,64,8,4,Hc,3>,
                             cudaFuncAttributeMaxDynamicSharedMemorySize, SMEM2);
        cudaFuncSetAttribute((const void*)dist1_kernel,
                             cudaFuncAttributeMaxDynamicSharedMemorySize, SMEMD1);
        init = true;
    }

    prep_kernel<<<N4TOT / 512, 512>>>(x, fc1_w, fc2_w, learn_w);

    mma_gemm<64,128,8,2,Dc,1><<<dim3(Hc/128, MR/64), 256, SMEM1>>>(
        xhi, xlo, w1hi, w1lo, fc1_b, nullptr);
    mma_gemm<128,64,8,4,Hc,3><<<dim3(Dc/64, MR/128, 3), 256, SMEM2>>>(
        hhi, hlo, w2hi, w2lo, nullptr, part);
    gemm2_epi<<<(MR * Dc / 4) / 256, 256>>>(fc2_b, learn_w, xhat);

    dist1_kernel<<<dim3(NPAIR, Bc), 256, SMEMD1>>>();
    dist2_kernel<<<dim3(Nc / 8, Bc), 256>>>(adj, box_num, soft);
}

// round 17
// speedup vs baseline: 1.0369x; 1.0369x over previous
#include <cuda_runtime.h>
#include <cuda_bf16.h>
#include <cstdint>
#include <cstddef>

#define Bc 8
#define Nc 384
#define Dc 256
#define Hc 1024
#define MR (Bc*Nc)   // 3072

// ----------------------------------------------------------------- scratch
__device__ __align__(128) float g_y[(size_t)MR * Dc];
__device__ __align__(128) float g_S[MR];
__device__ __align__(128) float g_dist[(size_t)Bc * Nc * Nc];
__device__ __align__(128) float g_part[3][(size_t)MR * Dc];
__device__ float g_sumw;
__device__ __align__(128) __nv_bfloat16 g_xhi[(size_t)MR * Dc],  g_xlo[(size_t)MR * Dc];
__device__ __align__(128) __nv_bfloat16 g_w1hi[(size_t)Hc * Dc], g_w1lo[(size_t)Hc * Dc];
__device__ __align__(128) __nv_bfloat16 g_w2hi[(size_t)Dc * Hc], g_w2lo[(size_t)Dc * Hc];
__device__ __align__(128) __nv_bfloat16 g_hhi[(size_t)MR * Hc],  g_hlo[(size_t)MR * Hc];

// ----------------------------------------------------------------- helpers
__device__ __forceinline__ uint32_t smem_u32(const void* p) {
    uint32_t a;
    asm("{ .reg .u64 t; cvta.to.shared.u64 t, %1; cvt.u32.u64 %0, t; }" : "=r"(a) : "l"(p));
    return a;
}
__device__ __forceinline__ void cp_async16(uint32_t dst, const void* src) {
    asm volatile("cp.async.cg.shared.global [%0], [%1], 16;\n" :: "r"(dst), "l"(src));
}
#define CP_COMMIT()  asm volatile("cp.async.commit_group;\n" ::: "memory")
#define CP_WAIT0()   asm volatile("cp.async.wait_group 0;\n" ::: "memory")
#define CP_WAIT1()   asm volatile("cp.async.wait_group 1;\n" ::: "memory")

__device__ __forceinline__ void ldsm_x4(uint32_t* r, uint32_t addr) {
    asm volatile("ldmatrix.sync.aligned.m8n8.x4.shared.b16 {%0,%1,%2,%3}, [%4];"
        : "=r"(r[0]), "=r"(r[1]), "=r"(r[2]), "=r"(r[3]) : "r"(addr));
}
__device__ __forceinline__ void mma_bf16(float* c, const uint32_t* a, const uint32_t* b) {
    asm volatile(
        "mma.sync.aligned.m16n8k16.row.col.f32.bf16.bf16.f32 "
        "{%0,%1,%2,%3}, {%4,%5,%6,%7}, {%8,%9}, {%0,%1,%2,%3};"
        : "+f"(c[0]), "+f"(c[1]), "+f"(c[2]), "+f"(c[3])
        : "r"(a[0]), "r"(a[1]), "r"(a[2]), "r"(a[3]), "r"(b[0]), "r"(b[1]));
}
__device__ __forceinline__ uint32_t cvt_bf16x2(float hi, float lo) {
    uint32_t r; asm("cvt.rn.bf16x2.f32 %0, %1, %2;" : "=r"(r) : "f"(hi), "f"(lo)); return r;
}

// ----------------------------------------------------------------- fused prep
#define N4X ((MR * Dc) / 4)
#define N4W ((Hc * Dc) / 4)
#define N4TOT (N4X + 2 * N4W)

__global__ __launch_bounds__(512) void prep_kernel(
    const float* __restrict__ x, const float* __restrict__ w1,
    const float* __restrict__ w2, const float* __restrict__ lw)
{
    const int gid = blockIdx.x * 512 + threadIdx.x;

    const float* src;
    __nv_bfloat16 *hi, *lo;
    int idx;
    if (gid < N4X)            { src = x;  hi = g_xhi;  lo = g_xlo;  idx = gid; }
    else if (gid < N4X + N4W) { src = w1; hi = g_w1hi; lo = g_w1lo; idx = gid - N4X; }
    else                      { src = w2; hi = g_w2hi; lo = g_w2lo; idx = gid - N4X - N4W; }

    const float4 v = *(const float4*)(src + 4 * (size_t)idx);
    uint2 hw, lw4;
    hw.x = cvt_bf16x2(v.y, v.x);
    hw.y = cvt_bf16x2(v.w, v.z);
    {
        const float h0 = __uint_as_float(hw.x << 16);
        const float h1 = __uint_as_float(hw.x & 0xffff0000u);
        const float h2 = __uint_as_float(hw.y << 16);
        const float h3 = __uint_as_float(hw.y & 0xffff0000u);
        lw4.x = cvt_bf16x2(v.y - h1, v.x - h0);
        lw4.y = cvt_bf16x2(v.w - h3, v.z - h2);
    }
    *(uint2*)(hi + 4 * (size_t)idx) = hw;
    *(uint2*)(lo + 4 * (size_t)idx) = lw4;

    if (gid < MR) g_S[gid] = 0.f;

    if (blockIdx.x == 0 && threadIdx.x < 256) {
        __shared__ float sm[8];
        const int t = threadIdx.x;
        float s = lw[t];
        #pragma unroll
        for (int off = 16; off; off >>= 1) s += __shfl_xor_sync(0xffffffffu, s, off);
        if ((t & 31) == 0) sm[t >> 5] = s;
        __syncthreads();
        if (t == 0) {
            float acc = 0.f;
            #pragma unroll
            for (int k = 0; k < 8; k++) acc += sm[k];
            g_sumw = acc;
        }
    }
}

// ----------------------------------------------------------------- mma.sync GEMM
// EPI=1: full-K, relu -> hidden hi/lo bf16.
// EPI=3: split-K partial (blockIdx.z selects k-range), raw accum -> out buffer z.
template<int BM, int BN, int NW, int WMF, int K, int EPI>
__global__ void __launch_bounds__(NW * 32) mma_gemm(
    const __nv_bfloat16* __restrict__ Ahi, const __nv_bfloat16* __restrict__ Alo,
    const __nv_bfloat16* __restrict__ Bhi, const __nv_bfloat16* __restrict__ Blo,
    const float* __restrict__ bias,
    float* __restrict__ out)
{
    constexpr int NT  = NW * 32;
    constexpr int WN  = BN / (NW / WMF);
    constexpr int NN  = WN / 8;
    constexpr int TA  = BM * 80;
    constexpr int TB  = BN * 80;
    constexpr int BUF = 2 * TA + 2 * TB;
    constexpr int NCH = K / 32;
    constexpr int OUTD = (EPI == 1) ? Hc : Dc;

    extern __shared__ __align__(1024) char smem[];
    float* s_bias = (float*)smem;
    const uint32_t tiles = smem_u32(smem) + 1024;

    const int tid  = threadIdx.x;
    const int wid  = tid >> 5, lane = tid & 31;
    const int m0   = blockIdx.y * BM, n0 = blockIdx.x * BN;
    const int wm   = (wid % WMF) * 32;
    const int wn   = (wid / WMF) * WN;

    int c0 = 0, c1 = NCH;
    float* po = out;
    if (EPI == 3) {
        const int z = blockIdx.z;
        c0 = z * 11;
        c1 = (z == 2) ? NCH : c0 + 11;
        po = out + (size_t)z * ((size_t)MR * Dc);
    }

    if (EPI == 1 && tid < BN) s_bias[tid] = bias[n0 + tid];

    float cacc[2][NN][4];
    #pragma unroll
    for (int f = 0; f < 2; f++)
        #pragma unroll
        for (int g = 0; g < NN; g++)
            #pragma unroll
            for (int e = 0; e < 4; e++) cacc[f][g][e] = 0.f;

    auto issue = [&](int c) {
        const uint32_t tb = tiles + (c & 1) * BUF;
        const int kc = c * 32;
        #pragma unroll
        for (int q = 0; q < (BM * 8) / NT; ++q) {
            const int id = q * NT + tid;
            const int mat = id / (BM * 4), e = id % (BM * 4);
            const int r = e >> 2, c16 = e & 3;
            const __nv_bfloat16* src = (mat ? Alo : Ahi) + (size_t)(m0 + r) * K + kc + c16 * 8;
            cp_async16(tb + mat * TA + r * 80 + c16 * 16, src);
        }
        #pragma unroll
        for (int q = 0; q < (BN * 8) / NT; ++q) {
            const int id = q * NT + tid;
            const int mat = id / (BN * 4), e = id % (BN * 4);
            const int r = e >> 2, c16 = e & 3;
            const __nv_bfloat16* src = (mat ? Blo : Bhi) + (size_t)(n0 + r) * K + kc + c16 * 8;
            cp_async16(tb + 2 * TA + mat * TB + r * 80 + c16 * 16, src);
        }
        CP_COMMIT();
    };

    issue(c0);
    issue(c0 + 1);

    for (int c = c0; c < c1; ++c) {
        if (c + 1 < c1) { CP_WAIT1(); } else { CP_WAIT0(); }
        __syncthreads();

        const uint32_t aBase = tiles + (c & 1) * BUF;
        const uint32_t bBase = aBase + 2 * TA;

        #pragma unroll
        for (int s = 0; s < 2; ++s) {
            const int kk = s * 16;
            uint32_t aH[2][4], aL[2][4];
            #pragma unroll
            for (int f = 0; f < 2; ++f) {
                const int row = wm + f * 16 + (lane & 15);
                const int col = kk + ((lane >> 4) << 3);
                const uint32_t ad = aBase + row * 80 + col * 2;
                ldsm_x4(aH[f], ad);
                ldsm_x4(aL[f], ad + TA);
            }
            #pragma unroll
            for (int np = 0; np < NN / 2; ++np) {
                const int rowB = wn + np * 16 + (lane & 7) + ((lane & 16) >> 1);
                const int colB = kk + (lane & 8);
                const uint32_t bd = bBase + rowB * 80 + colB * 2;
                uint32_t bH[4], bL[4];
                ldsm_x4(bH, bd);
                ldsm_x4(bL, bd + TB);
                #pragma unroll
                for (int f = 0; f < 2; ++f)
                    #pragma unroll
                    for (int h = 0; h < 2; ++h)
                        mma_bf16(cacc[f][2 * np + h], aH[f], bH + 2 * h);
                #pragma unroll
                for (int f = 0; f < 2; ++f)
                    #pragma unroll
                    for (int h = 0; h < 2; ++h)
                        mma_bf16(cacc[f][2 * np + h], aH[f], bL + 2 * h);
                #pragma unroll
                for (int f = 0; f < 2; ++f)
                    #pragma unroll
                    for (int h = 0; h < 2; ++h)
                        mma_bf16(cacc[f][2 * np + h], aL[f], bH + 2 * h);
            }
        }
        __syncthreads();
        if (c + 2 < c1) issue(c + 2);
    }

    const int tq = lane >> 2, tr = lane & 3;
    #pragma unroll
    for (int f = 0; f < 2; ++f) {
        #pragma unroll
        for (int g = 0; g < NN; ++g) {
            const int col  = n0 + wn + g * 8 + tr * 2;
            const int bcol = wn + g * 8 + tr * 2;
            #pragma unroll
            for (int half = 0; half < 2; ++half) {
                const int row = m0 + wm + f * 16 + tq + half * 8;
                if (EPI == 1) {
                    float v0 = fmaxf(cacc[f][g][2 * half]     + s_bias[bcol], 0.f);
                    float v1 = fmaxf(cacc[f][g][2 * half + 1] + s_bias[bcol + 1], 0.f);
                    const uint32_t h = cvt_bf16x2(v1, v0);
                    const float h0 = __uint_as_float(h << 16);
                    const float h1 = __uint_as_float(h & 0xffff0000u);
                    const uint32_t l = cvt_bf16x2(v1 - h1, v0 - h0);
                    *(uint32_t*)&g_hhi[(size_t)row * OUTD + col] = h;
                    *(uint32_t*)&g_hlo[(size_t)row * OUTD + col] = l;
                } else {
                    *(float2*)&po[(size_t)row * OUTD + col] =
                        make_float2(cacc[f][g][2 * half], cacc[f][g][2 * half + 1]);
                }
            }
        }
    }
}

// ----------------------------------------------------------------- gemm2 epilogue
__global__ __launch_bounds__(256) void gemm2_epi(
    const float* __restrict__ bias, const float* __restrict__ wvec,
    float* __restrict__ xhat)
{
    const int gid = blockIdx.x * 256 + threadIdx.x;   // 0..196607
    const int row = gid >> 6, q = gid & 63;
    const int col = q * 4;

    const float4 a0 = *(const float4*)&g_part[0][4 * (size_t)gid];
    const float4 a1 = *(const float4*)&g_part[1][4 * (size_t)gid];
    const float4 a2 = *(const float4*)&g_part[2][4 * (size_t)gid];
    const float4 b4 = *(const float4*)&bias[col];
    const float4 w4 = *(const float4*)&wvec[col];

    float4 v;
    v.x = a0.x + a1.x + a2.x + b4.x;
    v.y = a0.y + a1.y + a2.y + b4.y;
    v.z = a0.z + a1.z + a2.z + b4.z;
    v.w = a0.w + a1.w + a2.w + b4.w;

    float4 yv;
    yv.x = v.x * w4.x; yv.y = v.y * w4.y; yv.z = v.z * w4.z; yv.w = v.w * w4.w;

    *(float4*)&xhat[4 * (size_t)gid] = v;
    *(float4*)&g_y [4 * (size_t)gid] = yv;

    float s = (yv.x + yv.y) + (yv.z + yv.w);
    #pragma unroll
    for (int off = 16; off; off >>= 1) s += __shfl_xor_sync(0xffffffffu, s, off);
    if ((threadIdx.x & 31) == 0) atomicAdd(&g_S[row], s);
}

// ----------------------------------------------------------------- dist1
#define NTILE  8
#define NPAIR  36
#define TP     48
#define CHP    132
#define CHSZ   (2 * TP * CHP)

__global__ __launch_bounds__(256, 2) void dist1_kernel()
{
    extern __shared__ __align__(16) float sm[];
    float* s_tr = sm;

    const int tid = threadIdx.x;
    const int b = blockIdx.y;

    int rem = blockIdx.x, ti = 0;
    while (rem >= NTILE - ti) { rem -= NTILE - ti; ti++; }
    const int tj = ti + rem;
    const int i0 = ti * TP, j0 = tj * TP;

    const float* yb = g_y + (size_t)b * Nc * Dc;
    const uint32_t smb = smem_u32(sm);

    auto load_chunk = [&](int c) {
        const uint32_t base = smb + (uint32_t)((c & 1) * CHSZ * 4);
        const int dof = c * 128;
        #pragma unroll
        for (int q = 0; q < 6; ++q) {
            const int idx = q * 256 + tid;
            const int r = idx >> 5, u = idx & 31;
            cp_async16(base + (uint32_t)((r * 33 + u) << 4),
                       &yb[(size_t)(i0 + r) * Dc + dof + u * 4]);
        }
        #pragma unroll
        for (int q = 0; q < 6; ++q) {
            const int idx = q * 256 + tid;
            const int r = idx >> 5, u = idx & 31;
            cp_async16(base + (uint32_t)((TP * 33 + r * 33 + u) << 4),
                       &yb[(size_t)(j0 + r) * Dc + dof + u * 4]);
        }
        CP_COMMIT();
    };

    load_chunk(0);
    load_chunk(1);

    const int il = (tid >> 4) * 3;
    const int jl = (tid & 15) * 3;

    float acc[3][3];
    #pragma unroll
    for (int a = 0; a < 3; ++a)
        #pragma unroll
        for (int c = 0; c < 3; ++c) acc[a][c] = 0.f;

    #pragma unroll
    for (int ck = 0; ck < 2; ++ck) {
        if (ck == 0) { CP_WAIT1(); } else { CP_WAIT0(); }
        __syncthreads();

        const float* buf = sm + ck * CHSZ;
        const float* pi0 = buf + (il + 0) * CHP;
        const float* pi1 = buf + (il + 1) * CHP;
        const float* pi2 = buf + (il + 2) * CHP;
        const float* pj0 = buf + TP * CHP + (jl + 0) * CHP;
        const float* pj1 = buf + TP * CHP + (jl + 1) * CHP;
        const float* pj2 = buf + TP * CHP + (jl + 2) * CHP;

        #pragma unroll 8
        for (int u = 0; u < 32; ++u) {
            const int d = u << 2;
            const float4 xi0 = *(const float4*)(pi0 + d);
            const float4 xi1 = *(const float4*)(pi1 + d);
            const float4 xi2 = *(const float4*)(pi2 + d);
            const float4 xj0 = *(const float4*)(pj0 + d);
            const float4 xj1 = *(const float4*)(pj1 + d);
            const float4 xj2 = *(const float4*)(pj2 + d);
            acc[0][0] += fminf(xi0.x, xj0.x) + fminf(xi0.y, xj0.y) + fminf(xi0.z, xj0.z) + fminf(xi0.w, xj0.w);
            acc[0][1] += fminf(xi0.x, xj1.x) + fminf(xi0.y, xj1.y) + fminf(xi0.z, xj1.z) + fminf(xi0.w, xj1.w);
            acc[0][2] += fminf(xi0.x, xj2.x) + fminf(xi0.y, xj2.y) + fminf(xi0.z, xj2.z) + fminf(xi0.w, xj2.w);
            acc[1][0] += fminf(xi1.x, xj0.x) + fminf(xi1.y, xj0.y) + fminf(xi1.z, xj0.z) + fminf(xi1.w, xj0.w);
            acc[1][1] += fminf(xi1.x, xj1.x) + fminf(xi1.y, xj1.y) + fminf(xi1.z, xj1.z) + fminf(xi1.w, xj1.w);
            acc[1][2] += fminf(xi1.x, xj2.x) + fminf(xi1.y, xj2.y) + fminf(xi1.z, xj2.z) + fminf(xi1.w, xj2.w);
            acc[2][0] += fminf(xi2.x, xj0.x) + fminf(xi2.y, xj0.y) + fminf(xi2.z, xj0.z) + fminf(xi2.w, xj0.w);
            acc[2][1] += fminf(xi2.x, xj1.x) + fminf(xi2.y, xj1.y) + fminf(xi2.z, xj1.z) + fminf(xi2.w, xj1.w);
            acc[2][2] += fminf(xi2.x, xj2.x) + fminf(xi2.y, xj2.y) + fminf(xi2.z, xj2.z) + fminf(xi2.w, xj2.w);
        }
        if (ck == 0) __syncthreads();
    }

    float Si[3], Sj[3];
    #pragma unroll
    for (int a = 0; a < 3; ++a) {
        Si[a] = g_S[b * Nc + i0 + il + a];
        Sj[a] = g_S[b * Nc + j0 + jl + a];
    }
    float v[3][3];
    #pragma unroll
    for (int a = 0; a < 3; ++a)
        #pragma unroll
        for (int c = 0; c < 3; ++c)
            v[a][c] = Si[a] + Sj[c] - 2.f * acc[a][c];

    float* db = g_dist + (size_t)b * Nc * Nc;
    #pragma unroll
    for (int a = 0; a < 3; ++a)
        #pragma unroll
        for (int c = 0; c < 3; ++c)
            db[(size_t)(i0 + il + a) * Nc + j0 + jl + c] = v[a][c];

    if (ti != tj) {
        __syncthreads();
        #pragma unroll
        for (int a = 0; a < 3; ++a)
            #pragma unroll
            for (int c = 0; c < 3; ++c)
                s_tr[(jl + c) * 49 + il + a] = v[a][c];
        __syncthreads();
        #pragma unroll
        for (int a = 0; a < 3; ++a)
            #pragma unroll
            for (int c = 0; c < 3; ++c)
                db[(size_t)(j0 + il + a) * Nc + i0 + jl + c] = s_tr[(il + a) * 49 + jl + c];
    }
}

// ----------------------------------------------------------------- dist2
__global__ __launch_bounds__(256) void dist2_kernel(
    const float* __restrict__ adj,
    const int* __restrict__ box_num,
    float* __restrict__ out)
{
    const int tid = threadIdx.x;
    const int lane = tid & 31, wid = tid >> 5;
    const int b = blockIdx.y;
    const int i = blockIdx.x * 8 + wid;

    const int bn = box_num[b];
    const float sumw = g_sumw;
    const bool vi = i < bn;

    const float* drow = g_dist + ((size_t)b * Nc + i) * Nc;
    const float* arow = adj    + ((size_t)b * Nc + i) * Nc;
    float* orow       = out    + ((size_t)b * Nc + i) * Nc;

    float v[12];
    float mx = -3.4e38f;
    #pragma unroll
    for (int g = 0; g < 3; ++g) {
        const int j = g * 128 + lane * 4;
        const float4 d4 = *(const float4*)&drow[j];
        float t0 = d4.x, t1 = d4.y, t2 = d4.z, t3 = d4.w;
        if (!(vi && (j     < bn))) t0 -= sumw;
        if (!(vi && (j + 1 < bn))) t1 -= sumw;
        if (!(vi && (j + 2 < bn))) t2 -= sumw;
        if (!(vi && (j + 3 < bn))) t3 -= sumw;
        t0 = (t0 >= 0.f) ? t0 : 0.01f * t0;
        t1 = (t1 >= 0.f) ? t1 : 0.01f * t1;
        t2 = (t2 >= 0.f) ? t2 : 0.01f * t2;
        t3 = (t3 >= 0.f) ? t3 : 0.01f * t3;
        v[4 * g] = t0; v[4 * g + 1] = t1; v[4 * g + 2] = t2; v[4 * g + 3] = t3;
        mx = fmaxf(mx, fmaxf(fmaxf(t0, t1), fmaxf(t2, t3)));
    }
    #pragma unroll
    for (int off = 16; off; off >>= 1) mx = fmaxf(mx, __shfl_xor_sync(0xffffffffu, mx, off));

    float s = 0.f;
    #pragma unroll
    for (int g = 0; g < 3; ++g) {
        const int j = g * 128 + lane * 4;
        const float4 a4 = *(const float4*)&arow[j];
        const float e0 = a4.x * __expf(v[4 * g]     - mx);
        const float e1 = a4.y * __expf(v[4 * g + 1] - mx);
        const float e2 = a4.z * __expf(v[4 * g + 2] - mx);
        const float e3 = a4.w * __expf(v[4 * g + 3] - mx);
        v[4 * g] = e0; v[4 * g + 1] = e1; v[4 * g + 2] = e2; v[4 * g + 3] = e3;
        s += (e0 + e1) + (e2 + e3);
    }
    #pragma unroll
    for (int off = 16; off; off >>= 1) s += __shfl_xor_sync(0xffffffffu, s, off);
    const float inv = 1.f / s;

    #pragma unroll
    for (int g = 0; g < 3; ++g) {
        const int j = g * 128 + lane * 4;
        float4 o;
        o.x = v[4 * g]     * inv + 1e-10f;
        o.y = v[4 * g + 1] * inv + 1e-10f;
        o.z = v[4 * g + 2] * inv + 1e-10f;
        o.w = v[4 * g + 3] * inv + 1e-10f;
        *(float4*)&orow[j] = o;
    }
}

// ----------------------------------------------------------------- launch
#define SMEM1 (1024 + 2 * (2 * 64 * 80 + 2 * 128 * 80))    // 62464
#define SMEM2 (1024 + 2 * (2 * 128 * 80 + 2 * 128 * 80))   // 82944
#define SMEMD1 (2 * CHSZ * 4)                              // 101376

extern "C" void kernel_launch(void* const* d_in, const int* in_sizes, int n_in,
                              void* d_out, int out_size)
{
    const float* x       = (const float*)d_in[0];
    const float* adj     = (const float*)d_in[1];
    const int*   box_num = (const int*)d_in[2];
    const float* fc1_w   = (const float*)d_in[3];
    const float* fc1_b   = (const float*)d_in[4];
    const float* fc2_w   = (const float*)d_in[5];
    const float* fc2_b   = (const float*)d_in[6];
    const float* learn_w = (const float*)d_in[7];

    float* soft = (float*)d_out;                   // [8,384,384]
    float* xhat = soft + (size_t)Bc * Nc * Nc;     // [8,384,256]

    static __nv_bfloat16 *xhi, *xlo, *w1hi, *w1lo, *w2hi, *w2lo, *hhi, *hlo;
    static float* part;
    static bool init = false;
    if (!init) {
        cudaGetSymbolAddress((void**)&xhi,  g_xhi);
        cudaGetSymbolAddress((void**)&xlo,  g_xlo);
        cudaGetSymbolAddress((void**)&w1hi, g_w1hi);
        cudaGetSymbolAddress((void**)&w1lo, g_w1lo);
        cudaGetSymbolAddress((void**)&w2hi, g_w2hi);
        cudaGetSymbolAddress((void**)&w2lo, g_w2lo);
        cudaGetSymbolAddress((void**)&hhi,  g_hhi);
        cudaGetSymbolAddress((void**)&hlo,  g_hlo);
        cudaGetSymbolAddress((void**)&part, g_part);
        cudaFuncSetAttribute((const void*)mma_gemm<64,128,4,2,Dc,1>,
                             cudaFuncAttributeMaxDynamicSharedMemorySize, SMEM1);
        cudaFuncSetAttribute((const void*)mma_gemm<128,128,8,4,Hc,3>,
                             cudaFuncAttributeMaxDynamicSharedMemorySize, SMEM2);
        cudaFuncSetAttribute((const void*)dist1_kernel,
                             cudaFuncAttributeMaxDynamicSharedMemorySize, SMEMD1);
        init = true;
    }

    prep_kernel<<<N4TOT / 512, 512>>>(x, fc1_w, fc2_w, learn_w);

    mma_gemm<64,128,4,2,Dc,1><<<dim3(Hc/128, MR/64), 128, SMEM1>>>(
        xhi, xlo, w1hi, w1lo, fc1_b, nullptr);
    mma_gemm<128,128,8,4,Hc,3><<<dim3(Dc/128, MR/128, 3), 256, SMEM2>>>(
        hhi, hlo, w2hi, w2lo, nullptr, part);
    gemm2_epi<<<(MR * Dc / 4) / 256, 256>>>(fc2_b, learn_w, xhat);

    dist1_kernel<<<dim3(NPAIR, Bc), 256, SMEMD1>>>();
    dist2_kernel<<<dim3(Nc / 8, Bc), 256>>>(adj, box_num, soft);
}